// round 1
// baseline (speedup 1.0000x reference)
#include <cuda_runtime.h>

#define NN 100000
#define NE 1600000
#define C  128          // 4 branches x 32 hidden = aggregated channel width
#define NCLS 40

// ---------------- scratch (device globals; no allocation allowed) ----------
__device__ int   g_deg_out[NN];
__device__ int   g_deg_in[NN];
__device__ int   g_rowptr[NN + 1];
__device__ int   g_fill[NN];
__device__ int   g_col[NE];
__device__ float g_nsrc[NN];
__device__ float g_ndst[NN];
__device__ float g_A[(size_t)NN * C];   // aggregation results
__device__ float g_G[(size_t)NN * C];   // gather source for next layer

// ---------------- graph preprocessing --------------------------------------
__global__ void zero_kernel() {
    int i = blockIdx.x * blockDim.x + threadIdx.x;
    if (i < NN) { g_deg_out[i] = 0; g_deg_in[i] = 0; g_fill[i] = 0; }
}

__global__ void degree_kernel(const int* __restrict__ src, const int* __restrict__ dst) {
    int e = blockIdx.x * blockDim.x + threadIdx.x;
    if (e < NE) {
        atomicAdd(&g_deg_out[src[e]], 1);
        atomicAdd(&g_deg_in[dst[e]], 1);
    }
}

__global__ void norm_kernel() {
    int i = blockIdx.x * blockDim.x + threadIdx.x;
    if (i < NN) {
        g_nsrc[i] = rsqrtf(fmaxf((float)g_deg_out[i], 1.f));
        g_ndst[i] = rsqrtf(fmaxf((float)g_deg_in[i], 1.f));
    }
}

// Single-block exclusive scan of g_deg_in -> g_rowptr
__global__ void scan_kernel() {
    __shared__ int wsums[32];
    __shared__ int s_carry;
    int tid = threadIdx.x, lane = tid & 31, wid = tid >> 5;
    if (tid == 0) s_carry = 0;
    __syncthreads();
    for (int base = 0; base < NN; base += 1024) {
        int i = base + tid;
        int v = (i < NN) ? g_deg_in[i] : 0;
        int xv = v;
        #pragma unroll
        for (int o = 1; o < 32; o <<= 1) {
            int y = __shfl_up_sync(0xffffffffu, xv, o);
            if (lane >= o) xv += y;
        }
        if (lane == 31) wsums[wid] = xv;
        __syncthreads();
        if (wid == 0) {
            int wv = wsums[lane];
            #pragma unroll
            for (int o = 1; o < 32; o <<= 1) {
                int y = __shfl_up_sync(0xffffffffu, wv, o);
                if (lane >= o) wv += y;
            }
            wsums[lane] = wv;
        }
        __syncthreads();
        int incl = xv + (wid ? wsums[wid - 1] : 0) + s_carry;
        if (i < NN) g_rowptr[i] = incl - v;
        __syncthreads();
        if (tid == 1023) s_carry = incl;
        __syncthreads();
    }
    if (tid == 0) g_rowptr[NN] = s_carry;
}

__global__ void scatter_kernel(const int* __restrict__ src, const int* __restrict__ dst) {
    int e = blockIdx.x * blockDim.x + threadIdx.x;
    if (e < NE) {
        int d = dst[e];
        int pos = g_rowptr[d] + atomicAdd(&g_fill[d], 1);
        g_col[pos] = src[e];
    }
}

// ---------------- aggregation: warp per dst node ----------------------------
// A[w, :] = sum over incoming edges of in[src, :] (* nsrc[src] if SCALE)
template <bool SCALE>
__global__ void __launch_bounds__(256) agg_kernel(const float* __restrict__ xin) {
    const float* __restrict__ in = SCALE ? xin : (const float*)g_G;
    int w = blockIdx.x * 8 + (threadIdx.x >> 5);
    if (w >= NN) return;
    int lane4 = (threadIdx.x & 31) * 4;
    int e = g_rowptr[w], end = g_rowptr[w + 1];
    float a0 = 0.f, a1 = 0.f, a2 = 0.f, a3 = 0.f;
    for (; e + 3 < end; e += 4) {
        int s0 = g_col[e], s1 = g_col[e + 1], s2 = g_col[e + 2], s3 = g_col[e + 3];
        float4 v0 = *(const float4*)(in + (size_t)s0 * C + lane4);
        float4 v1 = *(const float4*)(in + (size_t)s1 * C + lane4);
        float4 v2 = *(const float4*)(in + (size_t)s2 * C + lane4);
        float4 v3 = *(const float4*)(in + (size_t)s3 * C + lane4);
        if (SCALE) {
            float c0 = g_nsrc[s0], c1 = g_nsrc[s1], c2 = g_nsrc[s2], c3 = g_nsrc[s3];
            a0 = fmaf(v0.x, c0, a0); a1 = fmaf(v0.y, c0, a1); a2 = fmaf(v0.z, c0, a2); a3 = fmaf(v0.w, c0, a3);
            a0 = fmaf(v1.x, c1, a0); a1 = fmaf(v1.y, c1, a1); a2 = fmaf(v1.z, c1, a2); a3 = fmaf(v1.w, c1, a3);
            a0 = fmaf(v2.x, c2, a0); a1 = fmaf(v2.y, c2, a1); a2 = fmaf(v2.z, c2, a2); a3 = fmaf(v2.w, c2, a3);
            a0 = fmaf(v3.x, c3, a0); a1 = fmaf(v3.y, c3, a1); a2 = fmaf(v3.z, c3, a2); a3 = fmaf(v3.w, c3, a3);
        } else {
            a0 += v0.x; a1 += v0.y; a2 += v0.z; a3 += v0.w;
            a0 += v1.x; a1 += v1.y; a2 += v1.z; a3 += v1.w;
            a0 += v2.x; a1 += v2.y; a2 += v2.z; a3 += v2.w;
            a0 += v3.x; a1 += v3.y; a2 += v3.z; a3 += v3.w;
        }
    }
    for (; e < end; e++) {
        int s = g_col[e];
        float4 v = *(const float4*)(in + (size_t)s * C + lane4);
        if (SCALE) {
            float c = g_nsrc[s];
            a0 = fmaf(v.x, c, a0); a1 = fmaf(v.y, c, a1);
            a2 = fmaf(v.z, c, a2); a3 = fmaf(v.w, c, a3);
        } else {
            a0 += v.x; a1 += v.y; a2 += v.z; a3 += v.w;
        }
    }
    float4 r; r.x = a0; r.y = a1; r.z = a2; r.w = a3;
    *(float4*)(g_A + (size_t)w * C + lane4) = r;
}

// ---------------- layer 0 transform: [64 nodes x 128] @ [128 x 128] ---------
// f0 = (A @ W0)*ndst + b0   (write to f0 output region)
// G  = relu(f0) * nsrc      (gather source for layer 1)
#define T0_SMEM ((128 * 128 + 128 * 68) * 4)
__global__ void __launch_bounds__(256) t0_kernel(const float* __restrict__ W0,
                                                 const float* __restrict__ b0,
                                                 float* __restrict__ f0out) {
    extern __shared__ float sm[];
    float* Ws = sm;             // [k][c], c = b*32+j
    float* As = sm + 128 * 128; // [k][n], stride 68
    int t = threadIdx.x;
    int node0 = blockIdx.x * 64;
    for (int i = t; i < 4 * 128 * 32; i += 256) {
        int b = i >> 12, k = (i >> 5) & 127, j = i & 31;
        Ws[k * 128 + b * 32 + j] = W0[i];
    }
    for (int i = t; i < 64 * 128; i += 256) {
        int k = i & 127, n = i >> 7;
        int gn = node0 + n;
        As[k * 68 + n] = (gn < NN) ? g_A[(size_t)gn * C + k] : 0.f;
    }
    __syncthreads();
    int c0 = (t & 31) * 4, nof = (t >> 5) * 8;
    float acc[8][4];
    #pragma unroll
    for (int n = 0; n < 8; n++)
        #pragma unroll
        for (int q = 0; q < 4; q++) acc[n][q] = 0.f;
    #pragma unroll 4
    for (int k = 0; k < 128; k++) {
        float4 w  = *(const float4*)&Ws[k * 128 + c0];
        float4 A0 = *(const float4*)&As[k * 68 + nof];
        float4 A1 = *(const float4*)&As[k * 68 + nof + 4];
        float av[8] = {A0.x, A0.y, A0.z, A0.w, A1.x, A1.y, A1.z, A1.w};
        #pragma unroll
        for (int n = 0; n < 8; n++) {
            acc[n][0] = fmaf(av[n], w.x, acc[n][0]);
            acc[n][1] = fmaf(av[n], w.y, acc[n][1]);
            acc[n][2] = fmaf(av[n], w.z, acc[n][2]);
            acc[n][3] = fmaf(av[n], w.w, acc[n][3]);
        }
    }
    int bb = c0 >> 5, j0 = c0 & 31;
    float4 bias = *(const float4*)&b0[c0];
    #pragma unroll
    for (int n = 0; n < 8; n++) {
        int gn = node0 + nof + n;
        if (gn >= NN) break;
        float nd = g_ndst[gn], ns = g_nsrc[gn];
        float4 f;
        f.x = fmaf(acc[n][0], nd, bias.x);
        f.y = fmaf(acc[n][1], nd, bias.y);
        f.z = fmaf(acc[n][2], nd, bias.z);
        f.w = fmaf(acc[n][3], nd, bias.w);
        *(float4*)&f0out[((size_t)bb * NN + gn) * 32 + j0] = f;
        float4 g;
        g.x = fmaxf(f.x, 0.f) * ns;
        g.y = fmaxf(f.y, 0.f) * ns;
        g.z = fmaxf(f.z, 0.f) * ns;
        g.w = fmaxf(f.w, 0.f) * ns;
        *(float4*)&g_G[(size_t)gn * C + c0] = g;
    }
}

// ---------------- layer 1 transform: block-diag [32x32] per branch ----------
__global__ void __launch_bounds__(256) t1_kernel(const float* __restrict__ W1,
                                                 const float* __restrict__ b1,
                                                 float* __restrict__ f1out) {
    __shared__ float Ws[4 * 1032];  // padded per-branch stride to avoid conflicts
    int t = threadIdx.x;
    for (int i = t; i < 4096; i += 256) {
        int b = i >> 10, r = i & 1023;
        Ws[b * 1032 + r] = W1[i];
    }
    __syncthreads();
    int n = blockIdx.x * 64 + (t >> 2);
    int b = t & 3;
    if (n >= NN) return;
    float in[32];
    const float* arow = g_A + (size_t)n * C + b * 32;
    #pragma unroll
    for (int q = 0; q < 8; q++) {
        float4 v = *(const float4*)(arow + q * 4);
        in[q * 4 + 0] = v.x; in[q * 4 + 1] = v.y; in[q * 4 + 2] = v.z; in[q * 4 + 3] = v.w;
    }
    float acc[32];
    #pragma unroll
    for (int j = 0; j < 32; j++) acc[j] = 0.f;
    #pragma unroll
    for (int kk = 0; kk < 32; kk++) {
        float a = in[kk];
        const float* wr = &Ws[b * 1032 + kk * 32];
        #pragma unroll
        for (int q = 0; q < 8; q++) {
            float4 w = *(const float4*)(wr + q * 4);
            acc[q * 4 + 0] = fmaf(a, w.x, acc[q * 4 + 0]);
            acc[q * 4 + 1] = fmaf(a, w.y, acc[q * 4 + 1]);
            acc[q * 4 + 2] = fmaf(a, w.z, acc[q * 4 + 2]);
            acc[q * 4 + 3] = fmaf(a, w.w, acc[q * 4 + 3]);
        }
    }
    float nd = g_ndst[n], ns = g_nsrc[n];
    const float* bb = b1 + b * 32;
    float* fo = f1out + ((size_t)b * NN + n) * 32;
    float* go = g_G + (size_t)n * C + b * 32;
    #pragma unroll
    for (int q = 0; q < 8; q++) {
        float4 bv = *(const float4*)(bb + q * 4);
        float4 f;
        f.x = fmaf(acc[q * 4 + 0], nd, bv.x);
        f.y = fmaf(acc[q * 4 + 1], nd, bv.y);
        f.z = fmaf(acc[q * 4 + 2], nd, bv.z);
        f.w = fmaf(acc[q * 4 + 3], nd, bv.w);
        *(float4*)(fo + q * 4) = f;
        float4 g;
        g.x = fmaxf(f.x, 0.f) * ns;
        g.y = fmaxf(f.y, 0.f) * ns;
        g.z = fmaxf(f.z, 0.f) * ns;
        g.w = fmaxf(f.w, 0.f) * ns;
        *(float4*)(go + q * 4) = g;
    }
}

// ---------------- output transform: [32 -> 40] per branch -------------------
__global__ void __launch_bounds__(256) t2_kernel(const float* __restrict__ Wout,
                                                 const float* __restrict__ bout,
                                                 float* __restrict__ outp) {
    __shared__ float Ws[4 * 1288];
    int t = threadIdx.x;
    for (int i = t; i < 4 * 1280; i += 256) {
        int b = i / 1280, r = i % 1280;
        Ws[b * 1288 + r] = Wout[i];
    }
    __syncthreads();
    int n = blockIdx.x * 64 + (t >> 2);
    int b = t & 3;
    if (n >= NN) return;
    float in[32];
    const float* arow = g_A + (size_t)n * C + b * 32;
    #pragma unroll
    for (int q = 0; q < 8; q++) {
        float4 v = *(const float4*)(arow + q * 4);
        in[q * 4 + 0] = v.x; in[q * 4 + 1] = v.y; in[q * 4 + 2] = v.z; in[q * 4 + 3] = v.w;
    }
    float acc[40];
    #pragma unroll
    for (int j = 0; j < 40; j++) acc[j] = 0.f;
    #pragma unroll
    for (int kk = 0; kk < 32; kk++) {
        float a = in[kk];
        const float* wr = &Ws[b * 1288 + kk * 40];
        #pragma unroll
        for (int q = 0; q < 10; q++) {
            float4 w = *(const float4*)(wr + q * 4);
            acc[q * 4 + 0] = fmaf(a, w.x, acc[q * 4 + 0]);
            acc[q * 4 + 1] = fmaf(a, w.y, acc[q * 4 + 1]);
            acc[q * 4 + 2] = fmaf(a, w.z, acc[q * 4 + 2]);
            acc[q * 4 + 3] = fmaf(a, w.w, acc[q * 4 + 3]);
        }
    }
    float nd = g_ndst[n];
    const float* bb = bout + b * 40;
    float* oo = outp + ((size_t)b * NN + n) * 40;
    #pragma unroll
    for (int q = 0; q < 10; q++) {
        float4 bv = *(const float4*)(bb + q * 4);
        float4 f;
        f.x = fmaf(acc[q * 4 + 0], nd, bv.x);
        f.y = fmaf(acc[q * 4 + 1], nd, bv.y);
        f.z = fmaf(acc[q * 4 + 2], nd, bv.z);
        f.w = fmaf(acc[q * 4 + 3], nd, bv.w);
        *(float4*)(oo + q * 4) = f;
    }
}

// ---------------- launch -----------------------------------------------------
extern "C" void kernel_launch(void* const* d_in, const int* in_sizes, int n_in,
                              void* d_out, int out_size) {
    const float* x    = (const float*)d_in[0];
    const int*   src  = (const int*)d_in[1];
    const int*   dst  = (const int*)d_in[2];
    const float* W0   = (const float*)d_in[3];
    const float* b0   = (const float*)d_in[4];
    const float* W1   = (const float*)d_in[5];
    const float* b1   = (const float*)d_in[6];
    const float* Wout = (const float*)d_in[7];
    const float* bout = (const float*)d_in[8];

    float* outp = (float*)d_out;                       // [4, N, 40]
    float* f0p  = outp + (size_t)4 * NN * NCLS;        // [4, N, 32]
    float* f1p  = f0p + (size_t)4 * NN * 32;           // [4, N, 32]

    cudaFuncSetAttribute(t0_kernel, cudaFuncAttributeMaxDynamicSharedMemorySize, T0_SMEM);

    int nb_nodes = (NN + 255) / 256;
    int nb_edges = (NE + 255) / 256;
    int nb_agg   = (NN + 7) / 8;
    int nb_t     = (NN + 63) / 64;

    zero_kernel<<<nb_nodes, 256>>>();
    degree_kernel<<<nb_edges, 256>>>(src, dst);
    norm_kernel<<<nb_nodes, 256>>>();
    scan_kernel<<<1, 1024>>>();
    scatter_kernel<<<nb_edges, 256>>>(src, dst);

    // layer 0: aggregate x*nsrc (shared across branches), then transform
    agg_kernel<true><<<nb_agg, 256>>>(x);
    t0_kernel<<<nb_t, 256, T0_SMEM>>>(W0, b0, f0p);

    // layer 1
    agg_kernel<false><<<nb_agg, 256>>>(nullptr);
    t1_kernel<<<nb_t, 256>>>(W1, b1, f1p);

    // layer 2 (aggregate 128ch, then expand to 160ch logits)
    agg_kernel<false><<<nb_agg, 256>>>(nullptr);
    t2_kernel<<<nb_t, 256>>>(Wout, bout, outp);
}

// round 3
// speedup vs baseline: 1.0537x; 1.0537x over previous
#include <cuda_runtime.h>
#include <cuda_fp16.h>

#define NN 100000
#define NE 1600000
#define C  128
#define NCLS 40
#define NB_SCAN 98   // ceil(NN/1024)

// ---------------- scratch ----------------------------------------------------
__device__ int   g_deg_out[NN];
__device__ int   g_deg_in[NN];
__device__ int   g_rowptr[NN + 1];
__device__ int   g_fill[NN];
__device__ int   g_col[NE];
__device__ int   g_blocksum[NB_SCAN];
__device__ int   g_blockoff[NB_SCAN];
__device__ float g_nsrc[NN];
__device__ float g_ndst[NN];
__device__ float g_A[(size_t)NN * C];     // fp32 aggregation results
__device__ uint2 g_Gh2[(size_t)NN * 32];  // fp16 gather source: 128 ch as 32x uint2 (4 half each)

// ---------------- packed f32x2 helpers --------------------------------------
__device__ __forceinline__ unsigned long long pk2(float a, float b) {
    unsigned long long r; asm("mov.b64 %0,{%1,%2};" : "=l"(r) : "f"(a), "f"(b)); return r;
}
__device__ __forceinline__ unsigned long long fma2(unsigned long long a, unsigned long long b,
                                                   unsigned long long c) {
    unsigned long long d;
    asm("fma.rn.f32x2 %0,%1,%2,%3;" : "=l"(d) : "l"(a), "l"(b), "l"(c));
    return d;
}
__device__ __forceinline__ float2 upk2(unsigned long long v) {
    float2 r; asm("mov.b64 {%0,%1},%2;" : "=f"(r.x), "=f"(r.y) : "l"(v)); return r;
}

// ---------------- graph preprocessing ---------------------------------------
__global__ void zero_kernel() {
    int i = blockIdx.x * blockDim.x + threadIdx.x;
    if (i < NN) { g_deg_out[i] = 0; g_deg_in[i] = 0; g_fill[i] = 0; }
}

__global__ void degree_kernel(const int* __restrict__ src, const int* __restrict__ dst) {
    int e = blockIdx.x * blockDim.x + threadIdx.x;
    if (e < NE) {
        atomicAdd(&g_deg_out[src[e]], 1);
        atomicAdd(&g_deg_in[dst[e]], 1);
    }
}

__global__ void norm_kernel() {
    int i = blockIdx.x * blockDim.x + threadIdx.x;
    if (i < NN) {
        g_nsrc[i] = rsqrtf(fmaxf((float)g_deg_out[i], 1.f));
        g_ndst[i] = rsqrtf(fmaxf((float)g_deg_in[i], 1.f));
    }
}

// x * nsrc -> fp16 gather buffer (layer-0 input)
__global__ void prescale_kernel(const float* __restrict__ x) {
    int i = blockIdx.x * blockDim.x + threadIdx.x;   // NN*32 threads, 4 ch each
    if (i >= NN * 32) return;
    int n = i >> 5, c = i & 31;
    float4 v = *(const float4*)(x + (size_t)n * C + c * 4);
    float s = g_nsrc[n];
    __half2 h0 = __floats2half2_rn(v.x * s, v.y * s);
    __half2 h1 = __floats2half2_rn(v.z * s, v.w * s);
    uint2 o; o.x = *(unsigned*)&h0; o.y = *(unsigned*)&h1;
    g_Gh2[(size_t)n * 32 + c] = o;
}

// ---------------- multi-block scan ------------------------------------------
__global__ void scan1_kernel() {   // block-local exclusive scan + block totals
    __shared__ int wsums[32];
    int tid = threadIdx.x, lane = tid & 31, wid = tid >> 5;
    int i = blockIdx.x * 1024 + tid;
    int v = (i < NN) ? g_deg_in[i] : 0;
    int xv = v;
    #pragma unroll
    for (int o = 1; o < 32; o <<= 1) {
        int y = __shfl_up_sync(0xffffffffu, xv, o);
        if (lane >= o) xv += y;
    }
    if (lane == 31) wsums[wid] = xv;
    __syncthreads();
    if (wid == 0) {
        int wv = wsums[lane];
        #pragma unroll
        for (int o = 1; o < 32; o <<= 1) {
            int y = __shfl_up_sync(0xffffffffu, wv, o);
            if (lane >= o) wv += y;
        }
        wsums[lane] = wv;
    }
    __syncthreads();
    int incl = xv + (wid ? wsums[wid - 1] : 0);
    if (i < NN) g_rowptr[i] = incl - v;
    if (tid == 1023) g_blocksum[blockIdx.x] = incl;
}

__global__ void scan2_kernel() {   // scan 98 block sums (1 block, 128 thr)
    __shared__ int s[128];
    int t = threadIdx.x;
    int v = (t < NB_SCAN) ? g_blocksum[t] : 0;
    s[t] = v;
    __syncthreads();
    #pragma unroll
    for (int o = 1; o < 128; o <<= 1) {
        int y = (t >= o) ? s[t - o] : 0;
        __syncthreads();
        s[t] += y;
        __syncthreads();
    }
    if (t < NB_SCAN) g_blockoff[t] = s[t] - v;
    if (t == 127) g_rowptr[NN] = s[127];
}

__global__ void scan3_kernel() {
    int i = blockIdx.x * blockDim.x + threadIdx.x;
    if (i < NN) g_rowptr[i] += g_blockoff[i >> 10];
}

__global__ void scatter_kernel(const int* __restrict__ src, const int* __restrict__ dst) {
    int e = blockIdx.x * blockDim.x + threadIdx.x;
    if (e < NE) {
        int d = dst[e];
        int pos = g_rowptr[d] + atomicAdd(&g_fill[d], 1);
        g_col[pos] = src[e];
    }
}

// ---------------- aggregation: warp per node, fp16 source --------------------
__global__ void __launch_bounds__(256) agg_kernel() {
    int w = blockIdx.x * 8 + (threadIdx.x >> 5);
    if (w >= NN) return;
    int lane = threadIdx.x & 31;
    int e = g_rowptr[w], end = g_rowptr[w + 1];
    float a0 = 0.f, a1 = 0.f, a2 = 0.f, a3 = 0.f;
    for (; e + 3 < end; e += 4) {
        int s0 = g_col[e], s1 = g_col[e + 1], s2 = g_col[e + 2], s3 = g_col[e + 3];
        uint2 u0 = g_Gh2[(size_t)s0 * 32 + lane];
        uint2 u1 = g_Gh2[(size_t)s1 * 32 + lane];
        uint2 u2 = g_Gh2[(size_t)s2 * 32 + lane];
        uint2 u3 = g_Gh2[(size_t)s3 * 32 + lane];
        float2 f;
        f = __half22float2(*(__half2*)&u0.x); a0 += f.x; a1 += f.y;
        f = __half22float2(*(__half2*)&u0.y); a2 += f.x; a3 += f.y;
        f = __half22float2(*(__half2*)&u1.x); a0 += f.x; a1 += f.y;
        f = __half22float2(*(__half2*)&u1.y); a2 += f.x; a3 += f.y;
        f = __half22float2(*(__half2*)&u2.x); a0 += f.x; a1 += f.y;
        f = __half22float2(*(__half2*)&u2.y); a2 += f.x; a3 += f.y;
        f = __half22float2(*(__half2*)&u3.x); a0 += f.x; a1 += f.y;
        f = __half22float2(*(__half2*)&u3.y); a2 += f.x; a3 += f.y;
    }
    for (; e < end; e++) {
        int s = g_col[e];
        uint2 u = g_Gh2[(size_t)s * 32 + lane];
        float2 f;
        f = __half22float2(*(__half2*)&u.x); a0 += f.x; a1 += f.y;
        f = __half22float2(*(__half2*)&u.y); a2 += f.x; a3 += f.y;
    }
    float4 r; r.x = a0; r.y = a1; r.z = a2; r.w = a3;
    *(float4*)(g_A + (size_t)w * C + lane * 4) = r;
}

// ---------------- layer 0: [128 nodes x 128] @ [128 x 128], f32x2 FMA --------
#define T0_PAD 136   // multiple of 4: float4 LDS.128 needs 16B alignment
#define T0_SMEM ((128 * 128 + 128 * T0_PAD) * 4)
__global__ void __launch_bounds__(256) t0_kernel(const float* __restrict__ W0,
                                                 const float* __restrict__ b0,
                                                 float* __restrict__ f0out) {
    extern __shared__ float sm[];
    float* Ws = sm;                  // [k][c]
    float* As = sm + 128 * 128;      // [k][n], stride T0_PAD
    int t = threadIdx.x;
    int node0 = blockIdx.x * 128;
    for (int i = t; i < 4 * 128 * 32; i += 256) {
        int b = i >> 12, k = (i >> 5) & 127, j = i & 31;
        Ws[k * 128 + b * 32 + j] = W0[i];
    }
    for (int i = t; i < 128 * 128; i += 256) {
        int k = i & 127, n = i >> 7;
        int gn = node0 + n;
        As[k * T0_PAD + n] = (gn < NN) ? g_A[(size_t)gn * C + k] : 0.f;
    }
    __syncthreads();

    int cH = (t & 15) * 4;        // cols cH..cH+3 and cH+64..cH+67
    int nB = (t >> 4) * 8;        // nodes nB..nB+7
    unsigned long long acc[8][4];
    #pragma unroll
    for (int n = 0; n < 8; n++)
        #pragma unroll
        for (int p = 0; p < 4; p++) acc[n][p] = 0ull;

    #pragma unroll 2
    for (int k = 0; k < 128; k++) {
        float4 wa = *(const float4*)&Ws[k * 128 + cH];
        float4 wb = *(const float4*)&Ws[k * 128 + cH + 64];
        unsigned long long w0 = pk2(wa.x, wa.y), w1 = pk2(wa.z, wa.w);
        unsigned long long w2 = pk2(wb.x, wb.y), w3 = pk2(wb.z, wb.w);
        float4 A0 = *(const float4*)&As[k * T0_PAD + nB];
        float4 A1 = *(const float4*)&As[k * T0_PAD + nB + 4];
        float av[8] = {A0.x, A0.y, A0.z, A0.w, A1.x, A1.y, A1.z, A1.w};
        #pragma unroll
        for (int n = 0; n < 8; n++) {
            unsigned long long ap = pk2(av[n], av[n]);
            acc[n][0] = fma2(ap, w0, acc[n][0]);
            acc[n][1] = fma2(ap, w1, acc[n][1]);
            acc[n][2] = fma2(ap, w2, acc[n][2]);
            acc[n][3] = fma2(ap, w3, acc[n][3]);
        }
    }

    int bA = cH >> 5, jA = cH & 31;
    int cB = cH + 64;
    int bB = cB >> 5, jB = cB & 31;
    float4 biasA = *(const float4*)&b0[cH];
    float4 biasB = *(const float4*)&b0[cB];
    #pragma unroll
    for (int n = 0; n < 8; n++) {
        int gn = node0 + nB + n;
        if (gn >= NN) break;
        float nd = g_ndst[gn], ns = g_nsrc[gn];
        float2 p0 = upk2(acc[n][0]), p1 = upk2(acc[n][1]);
        float2 p2 = upk2(acc[n][2]), p3 = upk2(acc[n][3]);
        float4 fa, fb;
        fa.x = fmaf(p0.x, nd, biasA.x); fa.y = fmaf(p0.y, nd, biasA.y);
        fa.z = fmaf(p1.x, nd, biasA.z); fa.w = fmaf(p1.y, nd, biasA.w);
        fb.x = fmaf(p2.x, nd, biasB.x); fb.y = fmaf(p2.y, nd, biasB.y);
        fb.z = fmaf(p3.x, nd, biasB.z); fb.w = fmaf(p3.y, nd, biasB.w);
        *(float4*)&f0out[((size_t)bA * NN + gn) * 32 + jA] = fa;
        *(float4*)&f0out[((size_t)bB * NN + gn) * 32 + jB] = fb;
        __half2 ga0 = __floats2half2_rn(fmaxf(fa.x, 0.f) * ns, fmaxf(fa.y, 0.f) * ns);
        __half2 ga1 = __floats2half2_rn(fmaxf(fa.z, 0.f) * ns, fmaxf(fa.w, 0.f) * ns);
        __half2 gb0 = __floats2half2_rn(fmaxf(fb.x, 0.f) * ns, fmaxf(fb.y, 0.f) * ns);
        __half2 gb1 = __floats2half2_rn(fmaxf(fb.z, 0.f) * ns, fmaxf(fb.w, 0.f) * ns);
        uint2 oa; oa.x = *(unsigned*)&ga0; oa.y = *(unsigned*)&ga1;
        uint2 ob; ob.x = *(unsigned*)&gb0; ob.y = *(unsigned*)&gb1;
        g_Gh2[(size_t)gn * 32 + (cH >> 2)] = oa;
        g_Gh2[(size_t)gn * 32 + (cB >> 2)] = ob;
    }
}

// ---------------- layer 1: block-diag [32x32] per branch ---------------------
__global__ void __launch_bounds__(256) t1_kernel(const float* __restrict__ W1,
                                                 const float* __restrict__ b1,
                                                 float* __restrict__ f1out) {
    __shared__ float Ws[4 * 1032];
    int t = threadIdx.x;
    for (int i = t; i < 4096; i += 256) {
        int b = i >> 10, r = i & 1023;
        Ws[b * 1032 + r] = W1[i];
    }
    __syncthreads();
    int n = blockIdx.x * 64 + (t >> 2);
    int b = t & 3;
    if (n >= NN) return;
    float in[32];
    const float* arow = g_A + (size_t)n * C + b * 32;
    #pragma unroll
    for (int q = 0; q < 8; q++) {
        float4 v = *(const float4*)(arow + q * 4);
        in[q * 4] = v.x; in[q * 4 + 1] = v.y; in[q * 4 + 2] = v.z; in[q * 4 + 3] = v.w;
    }
    float acc[32];
    #pragma unroll
    for (int j = 0; j < 32; j++) acc[j] = 0.f;
    #pragma unroll
    for (int kk = 0; kk < 32; kk++) {
        float a = in[kk];
        const float* wr = &Ws[b * 1032 + kk * 32];
        #pragma unroll
        for (int q = 0; q < 8; q++) {
            float4 w = *(const float4*)(wr + q * 4);
            acc[q * 4]     = fmaf(a, w.x, acc[q * 4]);
            acc[q * 4 + 1] = fmaf(a, w.y, acc[q * 4 + 1]);
            acc[q * 4 + 2] = fmaf(a, w.z, acc[q * 4 + 2]);
            acc[q * 4 + 3] = fmaf(a, w.w, acc[q * 4 + 3]);
        }
    }
    float nd = g_ndst[n], ns = g_nsrc[n];
    const float* bb = b1 + b * 32;
    float* fo = f1out + ((size_t)b * NN + n) * 32;
    #pragma unroll
    for (int q = 0; q < 8; q++) {
        float4 bv = *(const float4*)(bb + q * 4);
        float4 f;
        f.x = fmaf(acc[q * 4],     nd, bv.x);
        f.y = fmaf(acc[q * 4 + 1], nd, bv.y);
        f.z = fmaf(acc[q * 4 + 2], nd, bv.z);
        f.w = fmaf(acc[q * 4 + 3], nd, bv.w);
        *(float4*)(fo + q * 4) = f;
        __half2 g0 = __floats2half2_rn(fmaxf(f.x, 0.f) * ns, fmaxf(f.y, 0.f) * ns);
        __half2 g1 = __floats2half2_rn(fmaxf(f.z, 0.f) * ns, fmaxf(f.w, 0.f) * ns);
        uint2 o; o.x = *(unsigned*)&g0; o.y = *(unsigned*)&g1;
        g_Gh2[(size_t)n * 32 + b * 8 + q] = o;
    }
}

// ---------------- output: [32 -> 40] per branch ------------------------------
__global__ void __launch_bounds__(256) t2_kernel(const float* __restrict__ Wout,
                                                 const float* __restrict__ bout,
                                                 float* __restrict__ outp) {
    __shared__ float Ws[4 * 1288];
    int t = threadIdx.x;
    for (int i = t; i < 4 * 1280; i += 256) {
        int b = i / 1280, r = i % 1280;
        Ws[b * 1288 + r] = Wout[i];
    }
    __syncthreads();
    int n = blockIdx.x * 64 + (t >> 2);
    int b = t & 3;
    if (n >= NN) return;
    float in[32];
    const float* arow = g_A + (size_t)n * C + b * 32;
    #pragma unroll
    for (int q = 0; q < 8; q++) {
        float4 v = *(const float4*)(arow + q * 4);
        in[q * 4] = v.x; in[q * 4 + 1] = v.y; in[q * 4 + 2] = v.z; in[q * 4 + 3] = v.w;
    }
    float acc[40];
    #pragma unroll
    for (int j = 0; j < 40; j++) acc[j] = 0.f;
    #pragma unroll
    for (int kk = 0; kk < 32; kk++) {
        float a = in[kk];
        const float* wr = &Ws[b * 1288 + kk * 40];
        #pragma unroll
        for (int q = 0; q < 10; q++) {
            float4 w = *(const float4*)(wr + q * 4);
            acc[q * 4]     = fmaf(a, w.x, acc[q * 4]);
            acc[q * 4 + 1] = fmaf(a, w.y, acc[q * 4 + 1]);
            acc[q * 4 + 2] = fmaf(a, w.z, acc[q * 4 + 2]);
            acc[q * 4 + 3] = fmaf(a, w.w, acc[q * 4 + 3]);
        }
    }
    float nd = g_ndst[n];
    const float* bb = bout + b * 40;
    float* oo = outp + ((size_t)b * NN + n) * 40;
    #pragma unroll
    for (int q = 0; q < 10; q++) {
        float4 bv = *(const float4*)(bb + q * 4);
        float4 f;
        f.x = fmaf(acc[q * 4],     nd, bv.x);
        f.y = fmaf(acc[q * 4 + 1], nd, bv.y);
        f.z = fmaf(acc[q * 4 + 2], nd, bv.z);
        f.w = fmaf(acc[q * 4 + 3], nd, bv.w);
        *(float4*)(oo + q * 4) = f;
    }
}

// ---------------- launch ------------------------------------------------------
extern "C" void kernel_launch(void* const* d_in, const int* in_sizes, int n_in,
                              void* d_out, int out_size) {
    const float* x    = (const float*)d_in[0];
    const int*   src  = (const int*)d_in[1];
    const int*   dst  = (const int*)d_in[2];
    const float* W0   = (const float*)d_in[3];
    const float* b0   = (const float*)d_in[4];
    const float* W1   = (const float*)d_in[5];
    const float* b1   = (const float*)d_in[6];
    const float* Wout = (const float*)d_in[7];
    const float* bout = (const float*)d_in[8];

    float* outp = (float*)d_out;
    float* f0p  = outp + (size_t)4 * NN * NCLS;
    float* f1p  = f0p + (size_t)4 * NN * 32;

    cudaFuncSetAttribute(t0_kernel, cudaFuncAttributeMaxDynamicSharedMemorySize, T0_SMEM);

    int nb_nodes = (NN + 255) / 256;
    int nb_edges = (NE + 255) / 256;
    int nb_agg   = (NN + 7) / 8;
    int nb_t64   = (NN + 63) / 64;
    int nb_t128  = (NN + 127) / 128;
    int nb_pre   = (NN * 32 + 255) / 256;

    zero_kernel<<<nb_nodes, 256>>>();
    degree_kernel<<<nb_edges, 256>>>(src, dst);
    norm_kernel<<<nb_nodes, 256>>>();
    prescale_kernel<<<nb_pre, 256>>>(x);
    scan1_kernel<<<NB_SCAN, 1024>>>();
    scan2_kernel<<<1, 128>>>();
    scan3_kernel<<<nb_nodes, 256>>>();
    scatter_kernel<<<nb_edges, 256>>>(src, dst);

    agg_kernel<<<nb_agg, 256>>>();
    t0_kernel<<<nb_t128, 256, T0_SMEM>>>(W0, b0, f0p);

    agg_kernel<<<nb_agg, 256>>>();
    t1_kernel<<<nb_t64, 256>>>(W1, b1, f1p);

    agg_kernel<<<nb_agg, 256>>>();
    t2_kernel<<<nb_t64, 256>>>(Wout, bout, outp);
}

// round 4
// speedup vs baseline: 1.1775x; 1.1174x over previous
#include <cuda_runtime.h>
#include <cuda_fp16.h>

#define NN 100000
#define NE 1600000
#define C  128
#define NCLS 40
#define NB_SCAN 98   // ceil(NN/1024)

// ---------------- scratch ----------------------------------------------------
__device__ int   g_deg_out[NN];
__device__ int   g_deg_in[NN];
__device__ int   g_rowptr[NN + 1];
__device__ int   g_fill[NN];
__device__ int   g_col[NE];
__device__ int   g_blocksum[NB_SCAN];
__device__ int   g_blockoff[NB_SCAN];
__device__ float g_nsrc[NN];
__device__ float g_ndst[NN];
__device__ float g_A[(size_t)NN * C];     // fp32 aggregation results
__device__ uint2 g_Gh2[(size_t)NN * 32];  // fp16 gather source: 128 ch = 32x uint2

// ---------------- packed f32x2 helpers ---------------------------------------
__device__ __forceinline__ unsigned long long pk2(float a, float b) {
    unsigned long long r; asm("mov.b64 %0,{%1,%2};" : "=l"(r) : "f"(a), "f"(b)); return r;
}
__device__ __forceinline__ unsigned long long fma2(unsigned long long a, unsigned long long b,
                                                   unsigned long long c) {
    unsigned long long d;
    asm("fma.rn.f32x2 %0,%1,%2,%3;" : "=l"(d) : "l"(a), "l"(b), "l"(c));
    return d;
}
__device__ __forceinline__ float2 upk2(unsigned long long v) {
    float2 r; asm("mov.b64 {%0,%1},%2;" : "=f"(r.x), "=f"(r.y) : "l"(v)); return r;
}

// ---------------- graph preprocessing ----------------------------------------
__global__ void degree_kernel(const int* __restrict__ src, const int* __restrict__ dst) {
    int e = blockIdx.x * blockDim.x + threadIdx.x;
    if (e < NE) {
        atomicAdd(&g_deg_out[src[e]], 1);
        atomicAdd(&g_deg_in[dst[e]], 1);
    }
}

// norms + (x * nsrc -> fp16 gather buffer), fused
__global__ void prescale_kernel(const float* __restrict__ x) {
    int i = blockIdx.x * blockDim.x + threadIdx.x;   // NN*32 threads, 4 ch each
    if (i >= NN * 32) return;
    int n = i >> 5, c = i & 31;
    float s = rsqrtf(fmaxf((float)g_deg_out[n], 1.f));
    if (c == 0) {
        g_nsrc[n] = s;
        g_ndst[n] = rsqrtf(fmaxf((float)g_deg_in[n], 1.f));
    }
    float4 v = *(const float4*)(x + (size_t)n * C + c * 4);
    __half2 h0 = __floats2half2_rn(v.x * s, v.y * s);
    __half2 h1 = __floats2half2_rn(v.z * s, v.w * s);
    uint2 o; o.x = *(unsigned*)&h0; o.y = *(unsigned*)&h1;
    g_Gh2[(size_t)n * 32 + c] = o;
}

// ---------------- multi-block scan --------------------------------------------
__global__ void scan1_kernel() {
    __shared__ int wsums[32];
    int tid = threadIdx.x, lane = tid & 31, wid = tid >> 5;
    int i = blockIdx.x * 1024 + tid;
    int v = (i < NN) ? g_deg_in[i] : 0;
    int xv = v;
    #pragma unroll
    for (int o = 1; o < 32; o <<= 1) {
        int y = __shfl_up_sync(0xffffffffu, xv, o);
        if (lane >= o) xv += y;
    }
    if (lane == 31) wsums[wid] = xv;
    __syncthreads();
    if (wid == 0) {
        int wv = wsums[lane];
        #pragma unroll
        for (int o = 1; o < 32; o <<= 1) {
            int y = __shfl_up_sync(0xffffffffu, wv, o);
            if (lane >= o) wv += y;
        }
        wsums[lane] = wv;
    }
    __syncthreads();
    int incl = xv + (wid ? wsums[wid - 1] : 0);
    if (i < NN) g_rowptr[i] = incl - v;
    if (tid == 1023) g_blocksum[blockIdx.x] = incl;
}

__global__ void scan2_kernel() {
    __shared__ int s[128];
    int t = threadIdx.x;
    int v = (t < NB_SCAN) ? g_blocksum[t] : 0;
    s[t] = v;
    __syncthreads();
    #pragma unroll
    for (int o = 1; o < 128; o <<= 1) {
        int y = (t >= o) ? s[t - o] : 0;
        __syncthreads();
        s[t] += y;
        __syncthreads();
    }
    if (t < NB_SCAN) g_blockoff[t] = s[t] - v;
    if (t == 127) g_rowptr[NN] = s[127];
}

__global__ void scan3_kernel() {
    int i = blockIdx.x * blockDim.x + threadIdx.x;
    if (i < NN) g_rowptr[i] += g_blockoff[i >> 10];
}

__global__ void scatter_kernel(const int* __restrict__ src, const int* __restrict__ dst) {
    int e = blockIdx.x * blockDim.x + threadIdx.x;
    if (e < NE) {
        int d = dst[e];
        int pos = g_rowptr[d] + atomicAdd(&g_fill[d], 1);
        g_col[pos] = src[e];
    }
}

// ---------------- aggregation: warp/node, 8-wide MLP, pairwise fp16 add -------
__device__ __forceinline__ void acc_pair(uint2 ua, uint2 ub,
                                         float& a0, float& a1, float& a2, float& a3) {
    __half2 px = __hadd2(*(__half2*)&ua.x, *(__half2*)&ub.x);
    __half2 py = __hadd2(*(__half2*)&ua.y, *(__half2*)&ub.y);
    float2 f0 = __half22float2(px);
    float2 f1 = __half22float2(py);
    a0 += f0.x; a1 += f0.y; a2 += f1.x; a3 += f1.y;
}
__device__ __forceinline__ void acc_one(uint2 u,
                                        float& a0, float& a1, float& a2, float& a3) {
    float2 f0 = __half22float2(*(__half2*)&u.x);
    float2 f1 = __half22float2(*(__half2*)&u.y);
    a0 += f0.x; a1 += f0.y; a2 += f1.x; a3 += f1.y;
}

__global__ void __launch_bounds__(256) agg_kernel() {
    int w = blockIdx.x * 8 + (threadIdx.x >> 5);
    if (w >= NN) return;
    int lane = threadIdx.x & 31;
    int e = g_rowptr[w], end = g_rowptr[w + 1];
    float a0 = 0.f, a1 = 0.f, a2 = 0.f, a3 = 0.f;
    const uint2* __restrict__ G = g_Gh2;
    const int* __restrict__ col = g_col;
    for (; e + 7 < end; e += 8) {
        int s0 = col[e],     s1 = col[e + 1], s2 = col[e + 2], s3 = col[e + 3];
        int s4 = col[e + 4], s5 = col[e + 5], s6 = col[e + 6], s7 = col[e + 7];
        uint2 u0 = G[(size_t)s0 * 32 + lane];
        uint2 u1 = G[(size_t)s1 * 32 + lane];
        uint2 u2 = G[(size_t)s2 * 32 + lane];
        uint2 u3 = G[(size_t)s3 * 32 + lane];
        uint2 u4 = G[(size_t)s4 * 32 + lane];
        uint2 u5 = G[(size_t)s5 * 32 + lane];
        uint2 u6 = G[(size_t)s6 * 32 + lane];
        uint2 u7 = G[(size_t)s7 * 32 + lane];
        acc_pair(u0, u1, a0, a1, a2, a3);
        acc_pair(u2, u3, a0, a1, a2, a3);
        acc_pair(u4, u5, a0, a1, a2, a3);
        acc_pair(u6, u7, a0, a1, a2, a3);
    }
    for (; e + 1 < end; e += 2) {
        int s0 = col[e], s1 = col[e + 1];
        uint2 u0 = G[(size_t)s0 * 32 + lane];
        uint2 u1 = G[(size_t)s1 * 32 + lane];
        acc_pair(u0, u1, a0, a1, a2, a3);
    }
    if (e < end) {
        uint2 u = G[(size_t)col[e] * 32 + lane];
        acc_one(u, a0, a1, a2, a3);
    }
    float4 r; r.x = a0; r.y = a1; r.z = a2; r.w = a3;
    *(float4*)(g_A + (size_t)w * C + lane * 4) = r;
}

// ---------------- layer 0: [128 x 128] @ [128 x 128], 512 thr, f32x2 ---------
#define T0_PAD 132   // multiple of 4 (LDS.128 alignment); 4-way store conflicts
#define T0_SMEM ((128 * 128 + 128 * T0_PAD) * 4)
__global__ void __launch_bounds__(512) t0_kernel(const float* __restrict__ W0,
                                                 const float* __restrict__ b0,
                                                 float* __restrict__ f0out) {
    extern __shared__ float sm[];
    float* Ws = sm;                  // [k][c]
    float* As = sm + 128 * 128;      // [k][n], stride T0_PAD
    int t = threadIdx.x;
    int node0 = blockIdx.x * 128;
    for (int i = t; i < 4 * 128 * 32; i += 512) {
        int b = i >> 12, k = (i >> 5) & 127, j = i & 31;
        Ws[k * 128 + b * 32 + j] = W0[i];
    }
    for (int i = t; i < 128 * 128; i += 512) {
        int k = i & 127, n = i >> 7;
        int gn = node0 + n;
        As[k * T0_PAD + n] = (gn < NN) ? g_A[(size_t)gn * C + k] : 0.f;
    }
    __syncthreads();

    int cH = (t & 15) * 4;        // cols cH..cH+3 and cH+64..cH+67
    int nB = (t >> 4) * 4;        // nodes nB..nB+3 (t>>4 in 0..31)
    unsigned long long acc[4][4];
    #pragma unroll
    for (int n = 0; n < 4; n++)
        #pragma unroll
        for (int p = 0; p < 4; p++) acc[n][p] = 0ull;

    #pragma unroll 4
    for (int k = 0; k < 128; k++) {
        float4 wa = *(const float4*)&Ws[k * 128 + cH];
        float4 wb = *(const float4*)&Ws[k * 128 + cH + 64];
        unsigned long long w0 = pk2(wa.x, wa.y), w1 = pk2(wa.z, wa.w);
        unsigned long long w2 = pk2(wb.x, wb.y), w3 = pk2(wb.z, wb.w);
        float4 A0 = *(const float4*)&As[k * T0_PAD + nB];
        float av[4] = {A0.x, A0.y, A0.z, A0.w};
        #pragma unroll
        for (int n = 0; n < 4; n++) {
            unsigned long long ap = pk2(av[n], av[n]);
            acc[n][0] = fma2(ap, w0, acc[n][0]);
            acc[n][1] = fma2(ap, w1, acc[n][1]);
            acc[n][2] = fma2(ap, w2, acc[n][2]);
            acc[n][3] = fma2(ap, w3, acc[n][3]);
        }
    }

    int bA = cH >> 5, jA = cH & 31;
    int cB = cH + 64;
    int bB = cB >> 5, jB = cB & 31;
    float4 biasA = *(const float4*)&b0[cH];
    float4 biasB = *(const float4*)&b0[cB];
    #pragma unroll
    for (int n = 0; n < 4; n++) {
        int gn = node0 + nB + n;
        if (gn >= NN) break;
        float nd = g_ndst[gn], ns = g_nsrc[gn];
        float2 p0 = upk2(acc[n][0]), p1 = upk2(acc[n][1]);
        float2 p2 = upk2(acc[n][2]), p3 = upk2(acc[n][3]);
        float4 fa, fb;
        fa.x = fmaf(p0.x, nd, biasA.x); fa.y = fmaf(p0.y, nd, biasA.y);
        fa.z = fmaf(p1.x, nd, biasA.z); fa.w = fmaf(p1.y, nd, biasA.w);
        fb.x = fmaf(p2.x, nd, biasB.x); fb.y = fmaf(p2.y, nd, biasB.y);
        fb.z = fmaf(p3.x, nd, biasB.z); fb.w = fmaf(p3.y, nd, biasB.w);
        *(float4*)&f0out[((size_t)bA * NN + gn) * 32 + jA] = fa;
        *(float4*)&f0out[((size_t)bB * NN + gn) * 32 + jB] = fb;
        __half2 ga0 = __floats2half2_rn(fmaxf(fa.x, 0.f) * ns, fmaxf(fa.y, 0.f) * ns);
        __half2 ga1 = __floats2half2_rn(fmaxf(fa.z, 0.f) * ns, fmaxf(fa.w, 0.f) * ns);
        __half2 gb0 = __floats2half2_rn(fmaxf(fb.x, 0.f) * ns, fmaxf(fb.y, 0.f) * ns);
        __half2 gb1 = __floats2half2_rn(fmaxf(fb.z, 0.f) * ns, fmaxf(fb.w, 0.f) * ns);
        uint2 oa; oa.x = *(unsigned*)&ga0; oa.y = *(unsigned*)&ga1;
        uint2 ob; ob.x = *(unsigned*)&gb0; ob.y = *(unsigned*)&gb1;
        g_Gh2[(size_t)gn * 32 + (cH >> 2)] = oa;
        g_Gh2[(size_t)gn * 32 + (cB >> 2)] = ob;
    }
}

// ---------------- layer 1: block-diag [32x32] per branch ----------------------
__global__ void __launch_bounds__(256) t1_kernel(const float* __restrict__ W1,
                                                 const float* __restrict__ b1,
                                                 float* __restrict__ f1out) {
    __shared__ float Ws[4 * 1032];
    int t = threadIdx.x;
    for (int i = t; i < 4096; i += 256) {
        int b = i >> 10, r = i & 1023;
        Ws[b * 1032 + r] = W1[i];
    }
    __syncthreads();
    int n = blockIdx.x * 64 + (t >> 2);
    int b = t & 3;
    if (n >= NN) return;
    float in[32];
    const float* arow = g_A + (size_t)n * C + b * 32;
    #pragma unroll
    for (int q = 0; q < 8; q++) {
        float4 v = *(const float4*)(arow + q * 4);
        in[q * 4] = v.x; in[q * 4 + 1] = v.y; in[q * 4 + 2] = v.z; in[q * 4 + 3] = v.w;
    }
    float acc[32];
    #pragma unroll
    for (int j = 0; j < 32; j++) acc[j] = 0.f;
    #pragma unroll
    for (int kk = 0; kk < 32; kk++) {
        float a = in[kk];
        const float* wr = &Ws[b * 1032 + kk * 32];
        #pragma unroll
        for (int q = 0; q < 8; q++) {
            float4 w = *(const float4*)(wr + q * 4);
            acc[q * 4]     = fmaf(a, w.x, acc[q * 4]);
            acc[q * 4 + 1] = fmaf(a, w.y, acc[q * 4 + 1]);
            acc[q * 4 + 2] = fmaf(a, w.z, acc[q * 4 + 2]);
            acc[q * 4 + 3] = fmaf(a, w.w, acc[q * 4 + 3]);
        }
    }
    float nd = g_ndst[n], ns = g_nsrc[n];
    const float* bb = b1 + b * 32;
    float* fo = f1out + ((size_t)b * NN + n) * 32;
    #pragma unroll
    for (int q = 0; q < 8; q++) {
        float4 bv = *(const float4*)(bb + q * 4);
        float4 f;
        f.x = fmaf(acc[q * 4],     nd, bv.x);
        f.y = fmaf(acc[q * 4 + 1], nd, bv.y);
        f.z = fmaf(acc[q * 4 + 2], nd, bv.z);
        f.w = fmaf(acc[q * 4 + 3], nd, bv.w);
        *(float4*)(fo + q * 4) = f;
        __half2 g0 = __floats2half2_rn(fmaxf(f.x, 0.f) * ns, fmaxf(f.y, 0.f) * ns);
        __half2 g1 = __floats2half2_rn(fmaxf(f.z, 0.f) * ns, fmaxf(f.w, 0.f) * ns);
        uint2 o; o.x = *(unsigned*)&g0; o.y = *(unsigned*)&g1;
        g_Gh2[(size_t)n * 32 + b * 8 + q] = o;
    }
}

// ---------------- output: [32 -> 40] per branch --------------------------------
__global__ void __launch_bounds__(256) t2_kernel(const float* __restrict__ Wout,
                                                 const float* __restrict__ bout,
                                                 float* __restrict__ outp) {
    __shared__ float Ws[4 * 1288];
    int t = threadIdx.x;
    for (int i = t; i < 4 * 1280; i += 256) {
        int b = i / 1280, r = i % 1280;
        Ws[b * 1288 + r] = Wout[i];
    }
    __syncthreads();
    int n = blockIdx.x * 64 + (t >> 2);
    int b = t & 3;
    if (n >= NN) return;
    float in[32];
    const float* arow = g_A + (size_t)n * C + b * 32;
    #pragma unroll
    for (int q = 0; q < 8; q++) {
        float4 v = *(const float4*)(arow + q * 4);
        in[q * 4] = v.x; in[q * 4 + 1] = v.y; in[q * 4 + 2] = v.z; in[q * 4 + 3] = v.w;
    }
    float acc[40];
    #pragma unroll
    for (int j = 0; j < 40; j++) acc[j] = 0.f;
    #pragma unroll
    for (int kk = 0; kk < 32; kk++) {
        float a = in[kk];
        const float* wr = &Ws[b * 1288 + kk * 40];
        #pragma unroll
        for (int q = 0; q < 10; q++) {
            float4 w = *(const float4*)(wr + q * 4);
            acc[q * 4]     = fmaf(a, w.x, acc[q * 4]);
            acc[q * 4 + 1] = fmaf(a, w.y, acc[q * 4 + 1]);
            acc[q * 4 + 2] = fmaf(a, w.z, acc[q * 4 + 2]);
            acc[q * 4 + 3] = fmaf(a, w.w, acc[q * 4 + 3]);
        }
    }
    float nd = g_ndst[n];
    const float* bb = bout + b * 40;
    float* oo = outp + ((size_t)b * NN + n) * 40;
    #pragma unroll
    for (int q = 0; q < 10; q++) {
        float4 bv = *(const float4*)(bb + q * 4);
        float4 f;
        f.x = fmaf(acc[q * 4],     nd, bv.x);
        f.y = fmaf(acc[q * 4 + 1], nd, bv.y);
        f.z = fmaf(acc[q * 4 + 2], nd, bv.z);
        f.w = fmaf(acc[q * 4 + 3], nd, bv.w);
        *(float4*)(oo + q * 4) = f;
    }
}

// ---------------- launch --------------------------------------------------------
extern "C" void kernel_launch(void* const* d_in, const int* in_sizes, int n_in,
                              void* d_out, int out_size) {
    const float* x    = (const float*)d_in[0];
    const int*   src  = (const int*)d_in[1];
    const int*   dst  = (const int*)d_in[2];
    const float* W0   = (const float*)d_in[3];
    const float* b0   = (const float*)d_in[4];
    const float* W1   = (const float*)d_in[5];
    const float* b1   = (const float*)d_in[6];
    const float* Wout = (const float*)d_in[7];
    const float* bout = (const float*)d_in[8];

    float* outp = (float*)d_out;
    float* f0p  = outp + (size_t)4 * NN * NCLS;
    float* f1p  = f0p + (size_t)4 * NN * 32;

    cudaFuncSetAttribute(t0_kernel, cudaFuncAttributeMaxDynamicSharedMemorySize, T0_SMEM);

    void* p_deg_out; cudaGetSymbolAddress(&p_deg_out, g_deg_out);
    void* p_deg_in;  cudaGetSymbolAddress(&p_deg_in,  g_deg_in);
    void* p_fill;    cudaGetSymbolAddress(&p_fill,    g_fill);
    cudaMemsetAsync(p_deg_out, 0, NN * sizeof(int));
    cudaMemsetAsync(p_deg_in,  0, NN * sizeof(int));
    cudaMemsetAsync(p_fill,    0, NN * sizeof(int));

    int nb_nodes = (NN + 255) / 256;
    int nb_edges = (NE + 255) / 256;
    int nb_agg   = (NN + 7) / 8;
    int nb_t64   = (NN + 63) / 64;
    int nb_t128  = (NN + 127) / 128;
    int nb_pre   = (NN * 32 + 255) / 256;

    degree_kernel<<<nb_edges, 256>>>(src, dst);
    prescale_kernel<<<nb_pre, 256>>>(x);
    scan1_kernel<<<NB_SCAN, 1024>>>();
    scan2_kernel<<<1, 128>>>();
    scan3_kernel<<<nb_nodes, 256>>>();
    scatter_kernel<<<nb_edges, 256>>>(src, dst);

    agg_kernel<<<nb_agg, 256>>>();
    t0_kernel<<<nb_t128, 512, T0_SMEM>>>(W0, b0, f0p);

    agg_kernel<<<nb_agg, 256>>>();
    t1_kernel<<<nb_t64, 256>>>(W1, b1, f1p);

    agg_kernel<<<nb_agg, 256>>>();
    t2_kernel<<<nb_t64, 256>>>(Wout, bout, outp);
}